// round 2
// baseline (speedup 1.0000x reference)
#include <cuda_runtime.h>
#include <math.h>

#define NB 4
#define NT 2048
#define NC 1024
#define NH 16
#define ND 64
#define BT (NB*NT)   // 8192

// Scratch (static device globals: allowed; runtime allocation is not)
__device__ float g_q[NB*NH*NT*ND];  // [B,H,T,D], pre-scaled by 1/sqrt(D)
__device__ float g_k[NB*NH*NT*ND];
__device__ float g_v[NB*NH*NT*ND];
__device__ float g_y[BT*NC];        // attention output, [B,T,C]

// ---------------------------------------------------------------------------
// GEMM: out = alpha * (X @ W^T).  X [M=8192,K=1024] row-major, W [N=1024,K=1024]
// row-major (nn.Linear weight).  osel 0/1/2: scatter into g_q/g_k/g_v as
// [B,H,T,D]; osel 3: row-major [M,N] into outArg. xsel 1: read X from g_y.
// ---------------------------------------------------------------------------
__global__ __launch_bounds__(256) void gemm_xwt_kernel(
    const float* __restrict__ Xarg, const float* __restrict__ W,
    float* __restrict__ outArg, int xsel, int osel, float alpha)
{
    const float* X = xsel ? g_y : Xarg;
    float* out;
    if (osel == 0) out = g_q;
    else if (osel == 1) out = g_k;
    else if (osel == 2) out = g_v;
    else out = outArg;

    __shared__ float As[16][132];   // [k][m], padded
    __shared__ float Bs[16][132];   // [k][n], padded

    const int tid = threadIdx.x;
    const int tx = tid & 15;        // n-tile coord
    const int ty = tid >> 4;        // m-tile coord
    const int m0 = blockIdx.y * 128;
    const int n0 = blockIdx.x * 128;

    float acc[8][8];
#pragma unroll
    for (int i = 0; i < 8; i++)
#pragma unroll
        for (int j = 0; j < 8; j++) acc[i][j] = 0.f;

    for (int k0 = 0; k0 < NC; k0 += 16) {
#pragma unroll
        for (int l = 0; l < 2; l++) {
            int idx = tid + l * 256;          // 0..511
            int r = idx >> 2;                 // 0..127
            int c = idx & 3;                  // 0..3 (float4 column)
            float4 va = *(const float4*)(X + (size_t)(m0 + r) * NC + k0 + c * 4);
            As[c*4+0][r] = va.x; As[c*4+1][r] = va.y;
            As[c*4+2][r] = va.z; As[c*4+3][r] = va.w;
            float4 vb = *(const float4*)(W + (size_t)(n0 + r) * NC + k0 + c * 4);
            Bs[c*4+0][r] = vb.x; Bs[c*4+1][r] = vb.y;
            Bs[c*4+2][r] = vb.z; Bs[c*4+3][r] = vb.w;
        }
        __syncthreads();

#pragma unroll
        for (int k = 0; k < 16; k++) {
            float a[8], b[8];
#pragma unroll
            for (int i = 0; i < 8; i++) a[i] = As[k][ty * 8 + i];
#pragma unroll
            for (int j = 0; j < 8; j++) b[j] = Bs[k][tx * 8 + j];
#pragma unroll
            for (int i = 0; i < 8; i++)
#pragma unroll
                for (int j = 0; j < 8; j++)
                    acc[i][j] = fmaf(a[i], b[j], acc[i][j]);
        }
        __syncthreads();
    }

    // epilogue
#pragma unroll
    for (int i = 0; i < 8; i++) {
        int m = m0 + ty * 8 + i;
#pragma unroll
        for (int j4 = 0; j4 < 8; j4 += 4) {
            int n = n0 + tx * 8 + j4;
            float4 vv = make_float4(acc[i][j4+0] * alpha, acc[i][j4+1] * alpha,
                                    acc[i][j4+2] * alpha, acc[i][j4+3] * alpha);
            if (osel < 3) {
                int bb = m >> 11;          // m / 2048
                int t  = m & (NT - 1);
                int h  = n >> 6;           // n / 64
                int d  = n & 63;
                *(float4*)&out[(((size_t)bb * NH + h) * NT + t) * ND + d] = vv;
            } else {
                *(float4*)&out[(size_t)m * NC + n] = vv;
            }
        }
    }
}

// ---------------------------------------------------------------------------
// Flash attention, fp32.  64-query x 64-key tiles, D=64, online softmax.
// grid: (T/64, B*H), 256 threads.  Causal: only blockIdx.x+1 key tiles; mask
// applied only on the diagonal tile.  q is pre-scaled by 1/sqrt(D).
// Writes result into g_y as [B,T,C] (head-interleaved) for the final GEMM.
// ---------------------------------------------------------------------------
#define STRD 68   // 64 + 4 pad; 68 floats = 272B = 17*16 (16B-aligned rows)
#define ATT_SMEM ((4*64*STRD + 3*64) * sizeof(float))   // 70400 B

__global__ __launch_bounds__(256) void attn_kernel()
{
    extern __shared__ float sm[];
    float* Qs    = sm;                 // [64][STRD]
    float* Ks    = Qs + 64 * STRD;
    float* Vs    = Ks + 64 * STRD;
    float* Ss    = Vs + 64 * STRD;     // scores -> probs, in place
    float* rowm  = Ss + 64 * STRD;     // [64]
    float* rowl  = rowm + 64;
    float* rowsc = rowl + 64;

    const int tid = threadIdx.x;
    const int bh  = blockIdx.y;
    const int q0  = blockIdx.x * 64;

    const float* qp = g_q + (size_t)bh * NT * ND;
    const float* kp = g_k + (size_t)bh * NT * ND;
    const float* vp = g_v + (size_t)bh * NT * ND;

    // Load Q tile (64x64 floats = 1024 float4)
#pragma unroll
    for (int l = 0; l < 4; l++) {
        int idx = tid + l * 256;
        int r = idx >> 4, c = (idx & 15) * 4;
        *(float4*)&Qs[r * STRD + c] = *(const float4*)(qp + (size_t)(q0 + r) * ND + c);
    }
    if (tid < 64) { rowm[tid] = -INFINITY; rowl[tid] = 0.f; }

    const int tx = tid & 15;   // key/dim quad: c0 = tx*4
    const int ty = tid >> 4;   // query quad:   r0 = ty*4
    float o[4][4];
#pragma unroll
    for (int i = 0; i < 4; i++)
#pragma unroll
        for (int j = 0; j < 4; j++) o[i][j] = 0.f;

    __syncthreads();

    const int ntile = blockIdx.x + 1;
    for (int kt = 0; kt < ntile; kt++) {
        const int k0 = kt * 64;
        // Load K and V tiles
#pragma unroll
        for (int l = 0; l < 4; l++) {
            int idx = tid + l * 256;
            int r = idx >> 4, c = (idx & 15) * 4;
            *(float4*)&Ks[r * STRD + c] = *(const float4*)(kp + (size_t)(k0 + r) * ND + c);
            *(float4*)&Vs[r * STRD + c] = *(const float4*)(vp + (size_t)(k0 + r) * ND + c);
        }
        __syncthreads();

        // --- S = Q K^T (q already scaled) : 4x4 per thread ---
        float s[4][4];
#pragma unroll
        for (int i = 0; i < 4; i++)
#pragma unroll
            for (int j = 0; j < 4; j++) s[i][j] = 0.f;

#pragma unroll
        for (int d4 = 0; d4 < ND; d4 += 4) {
            float4 qv[4], kv[4];
#pragma unroll
            for (int i = 0; i < 4; i++) qv[i] = *(const float4*)&Qs[(ty*4+i)*STRD + d4];
#pragma unroll
            for (int j = 0; j < 4; j++) kv[j] = *(const float4*)&Ks[(tx*4+j)*STRD + d4];
#pragma unroll
            for (int i = 0; i < 4; i++)
#pragma unroll
                for (int j = 0; j < 4; j++) {
                    s[i][j] = fmaf(qv[i].x, kv[j].x, s[i][j]);
                    s[i][j] = fmaf(qv[i].y, kv[j].y, s[i][j]);
                    s[i][j] = fmaf(qv[i].z, kv[j].z, s[i][j]);
                    s[i][j] = fmaf(qv[i].w, kv[j].w, s[i][j]);
                }
        }

        if (k0 == q0) {   // diagonal tile: causal mask
#pragma unroll
            for (int i = 0; i < 4; i++)
#pragma unroll
                for (int j = 0; j < 4; j++)
                    if (k0 + tx*4 + j > q0 + ty*4 + i) s[i][j] = -INFINITY;
        }
#pragma unroll
        for (int i = 0; i < 4; i++) {
            float4 sv4 = make_float4(s[i][0], s[i][1], s[i][2], s[i][3]);
            *(float4*)&Ss[(ty*4+i)*STRD + tx*4] = sv4;
        }
        __syncthreads();

        // --- online softmax: 4 threads per row, 16 cols each ---
        {
            int row = tid >> 2, seg = tid & 3;
            float* srow = &Ss[row * STRD + seg * 16];
            float sv[16];
            float mloc = -INFINITY;
#pragma unroll
            for (int jj = 0; jj < 16; jj++) { sv[jj] = srow[jj]; mloc = fmaxf(mloc, sv[jj]); }
            mloc = fmaxf(mloc, __shfl_xor_sync(0xffffffffu, mloc, 1));
            mloc = fmaxf(mloc, __shfl_xor_sync(0xffffffffu, mloc, 2));
            float mold = rowm[row];
            float mnew = fmaxf(mold, mloc);
            float ssum = 0.f;
#pragma unroll
            for (int jj = 0; jj < 16; jj++) {
                float p = __expf(sv[jj] - mnew);
                ssum += p;
                srow[jj] = p;
            }
            ssum += __shfl_xor_sync(0xffffffffu, ssum, 1);
            ssum += __shfl_xor_sync(0xffffffffu, ssum, 2);
            if (seg == 0) {
                float sc = __expf(mold - mnew);   // 0 on first tile (mold=-inf)
                rowsc[row] = sc;
                rowl[row]  = rowl[row] * sc + ssum;
                rowm[row]  = mnew;
            }
        }
        __syncthreads();

        // --- O = O*scale + P V : 4 rows x 4 dims per thread ---
        {
            float sc[4];
#pragma unroll
            for (int i = 0; i < 4; i++) sc[i] = rowsc[ty*4 + i];
#pragma unroll
            for (int i = 0; i < 4; i++)
#pragma unroll
                for (int j = 0; j < 4; j++) o[i][j] *= sc[i];

#pragma unroll 8
            for (int jk = 0; jk < 64; jk++) {
                float4 vv = *(const float4*)&Vs[jk * STRD + tx*4];
#pragma unroll
                for (int i = 0; i < 4; i++) {
                    float p = Ss[(ty*4+i)*STRD + jk];
                    o[i][0] = fmaf(p, vv.x, o[i][0]);
                    o[i][1] = fmaf(p, vv.y, o[i][1]);
                    o[i][2] = fmaf(p, vv.z, o[i][2]);
                    o[i][3] = fmaf(p, vv.w, o[i][3]);
                }
            }
        }
        __syncthreads();
    }

    // epilogue: normalize and write to g_y [B,T,C]
    const int bb = bh >> 4;   // / NH
    const int h  = bh & 15;
#pragma unroll
    for (int i = 0; i < 4; i++) {
        int t = q0 + ty*4 + i;
        float inv = 1.f / rowl[ty*4 + i];
        float4 ov = make_float4(o[i][0]*inv, o[i][1]*inv, o[i][2]*inv, o[i][3]*inv);
        *(float4*)&g_y[((size_t)(bb * NT + t)) * NC + h * ND + tx*4] = ov;
    }
}

// ---------------------------------------------------------------------------
extern "C" void kernel_launch(void* const* d_in, const int* in_sizes, int n_in,
                              void* d_out, int out_size)
{
    const float* x  = (const float*)d_in[0];
    const float* Wq = (const float*)d_in[1];
    const float* Wk = (const float*)d_in[2];
    const float* Wv = (const float*)d_in[3];
    const float* Wp = (const float*)d_in[4];
    float* out = (float*)d_out;

    // idempotent, not stream-ordered -> capture-safe
    cudaFuncSetAttribute(attn_kernel, cudaFuncAttributeMaxDynamicSharedMemorySize,
                         (int)ATT_SMEM);

    dim3 ggrid(NC / 128, BT / 128);   // (8, 64)

    gemm_xwt_kernel<<<ggrid, 256>>>(x, Wq, nullptr, 0, 0, 0.125f); // Q, pre-scaled 1/sqrt(64)
    gemm_xwt_kernel<<<ggrid, 256>>>(x, Wk, nullptr, 0, 1, 1.0f);   // K
    gemm_xwt_kernel<<<ggrid, 256>>>(x, Wv, nullptr, 0, 2, 1.0f);   // V

    attn_kernel<<<dim3(NT / 64, NB * NH), 256, ATT_SMEM>>>();

    gemm_xwt_kernel<<<ggrid, 256>>>(nullptr, Wp, out, 1, 3, 1.0f); // out proj
}

// round 4
// speedup vs baseline: 1.4717x; 1.4717x over previous
#include <cuda_runtime.h>
#include <math.h>

#define NB 4
#define NT 2048
#define NC 1024
#define NH 16
#define ND 64
#define BT (NB*NT)   // 8192

// Scratch (static device globals)
__device__ float g_q[NB*NH*NT*ND];  // [B,H,T,D], pre-scaled by 1/sqrt(D)
__device__ float g_k[NB*NH*NT*ND];
__device__ float g_v[NB*NH*NT*ND];
__device__ float g_y[BT*NC];        // attention output, [B,T,C]

__device__ __forceinline__ unsigned f2tf32(float x) {
    unsigned r;
    asm("cvt.rna.tf32.f32 %0, %1;" : "=r"(r) : "f"(x));
    return r;
}

__device__ __forceinline__ void mma_tf32(float c[4], const unsigned a[4], const unsigned b[2]) {
    asm volatile(
        "mma.sync.aligned.m16n8k8.row.col.f32.tf32.tf32.f32 "
        "{%0,%1,%2,%3}, {%4,%5,%6,%7}, {%8,%9}, {%0,%1,%2,%3};"
        : "+f"(c[0]), "+f"(c[1]), "+f"(c[2]), "+f"(c[3])
        : "r"(a[0]), "r"(a[1]), "r"(a[2]), "r"(a[3]), "r"(b[0]), "r"(b[1]));
}

// ---------------------------------------------------------------------------
// tf32 tensor-core GEMM: out = alpha * (X @ W^T).
// X [8192,1024] row-major, W [1024,1024] row-major (nn.Linear weight).
// osel 0/1/2: scatter to g_q/g_k/g_v as [B,H,T,D]; osel 3: row-major to outArg.
// xsel 1: read X from g_y.
// Block tile 128x128, 8 warps (4m x 2n), warp tile 32x64, k-chunk 32.
// ---------------------------------------------------------------------------
__global__ __launch_bounds__(256, 2) void gemm_tf32_kernel(
    const float* __restrict__ Xarg, const float* __restrict__ W,
    float* __restrict__ outArg, int xsel, int osel, float alpha)
{
    const float* X = xsel ? g_y : Xarg;
    float* out;
    if (osel == 0) out = g_q;
    else if (osel == 1) out = g_k;
    else if (osel == 2) out = g_v;
    else out = outArg;

    __shared__ unsigned As[128][36];   // [m][k], pad 36
    __shared__ unsigned Bs[128][36];   // [n][k], pad 36

    const int tid  = threadIdx.x;
    const int lane = tid & 31;
    const int wid  = tid >> 5;
    const int wm   = (wid & 3) * 32;   // warp m offset
    const int wn   = (wid >> 2) * 64;  // warp n offset
    const int g    = lane >> 2;        // group id (0..7)
    const int t    = lane & 3;         // thread in group (0..3)
    const int m0   = blockIdx.y * 128;
    const int n0   = blockIdx.x * 128;

    float acc[2][8][4];
#pragma unroll
    for (int mt = 0; mt < 2; mt++)
#pragma unroll
        for (int nt = 0; nt < 8; nt++)
#pragma unroll
            for (int i = 0; i < 4; i++) acc[mt][nt][i] = 0.f;

    for (int k0 = 0; k0 < NC; k0 += 32) {
        // stage 128x32 of X and W into smem, converting to tf32 (rna)
#pragma unroll
        for (int l = 0; l < 4; l++) {
            int idx = tid + l * 256;       // 0..1023
            int r = idx >> 3;              // 0..127
            int c = (idx & 7) * 4;         // 0..28
            float4 va = *(const float4*)(X + (size_t)(m0 + r) * NC + k0 + c);
            uint4 ua = make_uint4(f2tf32(va.x), f2tf32(va.y), f2tf32(va.z), f2tf32(va.w));
            *(uint4*)&As[r][c] = ua;
            float4 vb = *(const float4*)(W + (size_t)(n0 + r) * NC + k0 + c);
            uint4 ub = make_uint4(f2tf32(vb.x), f2tf32(vb.y), f2tf32(vb.z), f2tf32(vb.w));
            *(uint4*)&Bs[r][c] = ub;
        }
        __syncthreads();

#pragma unroll
        for (int kk = 0; kk < 4; kk++) {
            const int kb = kk * 8;
            unsigned a[2][4], b[8][2];
#pragma unroll
            for (int mt = 0; mt < 2; mt++) {
                int row = wm + mt * 16 + g;
                a[mt][0] = As[row][kb + t];
                a[mt][1] = As[row + 8][kb + t];
                a[mt][2] = As[row][kb + t + 4];
                a[mt][3] = As[row + 8][kb + t + 4];
            }
#pragma unroll
            for (int nt = 0; nt < 8; nt++) {
                int col = wn + nt * 8 + g;
                b[nt][0] = Bs[col][kb + t];
                b[nt][1] = Bs[col][kb + t + 4];
            }
#pragma unroll
            for (int mt = 0; mt < 2; mt++)
#pragma unroll
                for (int nt = 0; nt < 8; nt++)
                    mma_tf32(acc[mt][nt], a[mt], b[nt]);
        }
        __syncthreads();
    }

    // epilogue: thread owns (g, t*2..t*2+1) and (+8) rows of each 16x8 tile
#pragma unroll
    for (int mt = 0; mt < 2; mt++) {
#pragma unroll
        for (int nt = 0; nt < 8; nt++) {
            int m1 = m0 + wm + mt * 16 + g;
            int n  = n0 + wn + nt * 8 + t * 2;
#pragma unroll
            for (int half = 0; half < 2; half++) {
                int m = m1 + half * 8;
                float2 vv = make_float2(acc[mt][nt][half*2] * alpha,
                                        acc[mt][nt][half*2+1] * alpha);
                if (osel < 3) {
                    int bb = m >> 11;
                    int tt = m & (NT - 1);
                    int h  = n >> 6;
                    int d  = n & 63;
                    *(float2*)&out[(((size_t)bb * NH + h) * NT + tt) * ND + d] = vv;
                } else {
                    *(float2*)&out[(size_t)m * NC + n] = vv;
                }
            }
        }
    }
}

// ---------------------------------------------------------------------------
// Flash attention, fp32 (unchanged from round 1).
// ---------------------------------------------------------------------------
#define STRD 68
#define ATT_SMEM ((4*64*STRD + 3*64) * sizeof(float))   // 70400 B

__global__ __launch_bounds__(256) void attn_kernel()
{
    extern __shared__ float sm[];
    float* Qs    = sm;
    float* Ks    = Qs + 64 * STRD;
    float* Vs    = Ks + 64 * STRD;
    float* Ss    = Vs + 64 * STRD;
    float* rowm  = Ss + 64 * STRD;
    float* rowl  = rowm + 64;
    float* rowsc = rowl + 64;

    const int tid = threadIdx.x;
    const int bh  = blockIdx.y;
    const int q0  = blockIdx.x * 64;

    const float* qp = g_q + (size_t)bh * NT * ND;
    const float* kp = g_k + (size_t)bh * NT * ND;
    const float* vp = g_v + (size_t)bh * NT * ND;

#pragma unroll
    for (int l = 0; l < 4; l++) {
        int idx = tid + l * 256;
        int r = idx >> 4, c = (idx & 15) * 4;
        *(float4*)&Qs[r * STRD + c] = *(const float4*)(qp + (size_t)(q0 + r) * ND + c);
    }
    if (tid < 64) { rowm[tid] = -INFINITY; rowl[tid] = 0.f; }

    const int tx = tid & 15;
    const int ty = tid >> 4;
    float o[4][4];
#pragma unroll
    for (int i = 0; i < 4; i++)
#pragma unroll
        for (int j = 0; j < 4; j++) o[i][j] = 0.f;

    __syncthreads();

    const int ntile = blockIdx.x + 1;
    for (int kt = 0; kt < ntile; kt++) {
        const int k0 = kt * 64;
#pragma unroll
        for (int l = 0; l < 4; l++) {
            int idx = tid + l * 256;
            int r = idx >> 4, c = (idx & 15) * 4;
            *(float4*)&Ks[r * STRD + c] = *(const float4*)(kp + (size_t)(k0 + r) * ND + c);
            *(float4*)&Vs[r * STRD + c] = *(const float4*)(vp + (size_t)(k0 + r) * ND + c);
        }
        __syncthreads();

        float s[4][4];
#pragma unroll
        for (int i = 0; i < 4; i++)
#pragma unroll
            for (int j = 0; j < 4; j++) s[i][j] = 0.f;

#pragma unroll
        for (int d4 = 0; d4 < ND; d4 += 4) {
            float4 qv[4], kv[4];
#pragma unroll
            for (int i = 0; i < 4; i++) qv[i] = *(const float4*)&Qs[(ty*4+i)*STRD + d4];
#pragma unroll
            for (int j = 0; j < 4; j++) kv[j] = *(const float4*)&Ks[(tx*4+j)*STRD + d4];
#pragma unroll
            for (int i = 0; i < 4; i++)
#pragma unroll
                for (int j = 0; j < 4; j++) {
                    s[i][j] = fmaf(qv[i].x, kv[j].x, s[i][j]);
                    s[i][j] = fmaf(qv[i].y, kv[j].y, s[i][j]);
                    s[i][j] = fmaf(qv[i].z, kv[j].z, s[i][j]);
                    s[i][j] = fmaf(qv[i].w, kv[j].w, s[i][j]);
                }
        }

        if (k0 == q0) {
#pragma unroll
            for (int i = 0; i < 4; i++)
#pragma unroll
                for (int j = 0; j < 4; j++)
                    if (k0 + tx*4 + j > q0 + ty*4 + i) s[i][j] = -INFINITY;
        }
#pragma unroll
        for (int i = 0; i < 4; i++) {
            float4 sv4 = make_float4(s[i][0], s[i][1], s[i][2], s[i][3]);
            *(float4*)&Ss[(ty*4+i)*STRD + tx*4] = sv4;
        }
        __syncthreads();

        {
            int row = tid >> 2, seg = tid & 3;
            float* srow = &Ss[row * STRD + seg * 16];
            float sv[16];
            float mloc = -INFINITY;
#pragma unroll
            for (int jj = 0; jj < 16; jj++) { sv[jj] = srow[jj]; mloc = fmaxf(mloc, sv[jj]); }
            mloc = fmaxf(mloc, __shfl_xor_sync(0xffffffffu, mloc, 1));
            mloc = fmaxf(mloc, __shfl_xor_sync(0xffffffffu, mloc, 2));
            float mold = rowm[row];
            float mnew = fmaxf(mold, mloc);
            float ssum = 0.f;
#pragma unroll
            for (int jj = 0; jj < 16; jj++) {
                float p = __expf(sv[jj] - mnew);
                ssum += p;
                srow[jj] = p;
            }
            ssum += __shfl_xor_sync(0xffffffffu, ssum, 1);
            ssum += __shfl_xor_sync(0xffffffffu, ssum, 2);
            if (seg == 0) {
                float sc = __expf(mold - mnew);
                rowsc[row] = sc;
                rowl[row]  = rowl[row] * sc + ssum;
                rowm[row]  = mnew;
            }
        }
        __syncthreads();

        {
            float sc[4];
#pragma unroll
            for (int i = 0; i < 4; i++) sc[i] = rowsc[ty*4 + i];
#pragma unroll
            for (int i = 0; i < 4; i++)
#pragma unroll
                for (int j = 0; j < 4; j++) o[i][j] *= sc[i];

#pragma unroll 8
            for (int jk = 0; jk < 64; jk++) {
                float4 vv = *(const float4*)&Vs[jk * STRD + tx*4];
#pragma unroll
                for (int i = 0; i < 4; i++) {
                    float p = Ss[(ty*4+i)*STRD + jk];
                    o[i][0] = fmaf(p, vv.x, o[i][0]);
                    o[i][1] = fmaf(p, vv.y, o[i][1]);
                    o[i][2] = fmaf(p, vv.z, o[i][2]);
                    o[i][3] = fmaf(p, vv.w, o[i][3]);
                }
            }
        }
        __syncthreads();
    }

    const int bb = bh >> 4;
    const int h  = bh & 15;
#pragma unroll
    for (int i = 0; i < 4; i++) {
        int tq = q0 + ty*4 + i;
        float inv = 1.f / rowl[ty*4 + i];
        float4 ov = make_float4(o[i][0]*inv, o[i][1]*inv, o[i][2]*inv, o[i][3]*inv);
        *(float4*)&g_y[((size_t)(bb * NT + tq)) * NC + h * ND + tx*4] = ov;
    }
}

// ---------------------------------------------------------------------------
extern "C" void kernel_launch(void* const* d_in, const int* in_sizes, int n_in,
                              void* d_out, int out_size)
{
    const float* x  = (const float*)d_in[0];
    const float* Wq = (const float*)d_in[1];
    const float* Wk = (const float*)d_in[2];
    const float* Wv = (const float*)d_in[3];
    const float* Wp = (const float*)d_in[4];
    float* out = (float*)d_out;

    cudaFuncSetAttribute(attn_kernel, cudaFuncAttributeMaxDynamicSharedMemorySize,
                         (int)ATT_SMEM);

    dim3 ggrid(NC / 128, BT / 128);   // (8, 64)

    gemm_tf32_kernel<<<ggrid, 256>>>(x, Wq, nullptr, 0, 0, 0.125f); // Q (1/sqrt(64) folded)
    gemm_tf32_kernel<<<ggrid, 256>>>(x, Wk, nullptr, 0, 1, 1.0f);   // K
    gemm_tf32_kernel<<<ggrid, 256>>>(x, Wv, nullptr, 0, 2, 1.0f);   // V

    attn_kernel<<<dim3(NT / 64, NB * NH), 256, ATT_SMEM>>>();

    gemm_tf32_kernel<<<ggrid, 256>>>(nullptr, Wp, out, 1, 3, 1.0f); // out proj
}

// round 6
// speedup vs baseline: 4.0524x; 2.7536x over previous
#include <cuda_runtime.h>
#include <math.h>

#define NB 4
#define NT 2048
#define NC 1024
#define NH 16
#define ND 64
#define BT (NB*NT)   // 8192

// Scratch (static device globals)
__device__ float g_q[NB*NH*NT*ND];   // [B,H,T,D], scaled by 0.125*log2(e)
__device__ float g_k[NB*NH*NT*ND];
__device__ float g_v[NB*NH*NT*ND];
__device__ float g_xt[BT*NC];        // tf32-rounded GEMM A input (x, then attn out)
__device__ float g_wq[NC*NC];        // tf32-rounded weights
__device__ float g_wk[NC*NC];
__device__ float g_wv[NC*NC];
__device__ float g_wp[NC*NC];

__device__ __forceinline__ unsigned f2tf32(float x) {
    unsigned r;
    asm("cvt.rna.tf32.f32 %0, %1;" : "=r"(r) : "f"(x));
    return r;
}

__device__ __forceinline__ void mma_tf32(float c[4], const unsigned a[4], const unsigned b[2]) {
    asm volatile(
        "mma.sync.aligned.m16n8k8.row.col.f32.tf32.tf32.f32 "
        "{%0,%1,%2,%3}, {%4,%5,%6,%7}, {%8,%9}, {%0,%1,%2,%3};"
        : "+f"(c[0]), "+f"(c[1]), "+f"(c[2]), "+f"(c[3])
        : "r"(a[0]), "r"(a[1]), "r"(a[2]), "r"(a[3]), "r"(b[0]), "r"(b[1]));
}

__device__ __forceinline__ void cp_async16(void* smem, const void* gmem) {
    unsigned s = (unsigned)__cvta_generic_to_shared(smem);
    asm volatile("cp.async.cg.shared.global [%0], [%1], 16;\n" :: "r"(s), "l"(gmem));
}
__device__ __forceinline__ void cp_commit() { asm volatile("cp.async.commit_group;\n" ::); }
template<int N> __device__ __forceinline__ void cp_wait() {
    asm volatile("cp.async.wait_group %0;\n" :: "n"(N));
}

// ---------------------------------------------------------------------------
// Elementwise rna-round to tf32 (bits stored as float). n multiple of 4.
// ---------------------------------------------------------------------------
__global__ void cvt_tf32_kernel(const float* __restrict__ src, float* __restrict__ dst, int n4)
{
    int i = blockIdx.x * blockDim.x + threadIdx.x;
    if (i < n4) {
        float4 v = ((const float4*)src)[i];
        uint4 u = make_uint4(f2tf32(v.x), f2tf32(v.y), f2tf32(v.z), f2tf32(v.w));
        ((uint4*)dst)[i] = u;
    }
}

// ---------------------------------------------------------------------------
// tf32 GEMM (cp.async, double-buffered): out = alpha * (X @ W^T).
// X, W are PRE-ROUNDED to tf32. Block 128x128, 8 warps (4m x 2n), k-chunk 32.
// osel 0/1/2: scatter to g_q/g_k/g_v as [B,H,T,D]; osel 3: row-major to outArg.
// ---------------------------------------------------------------------------
#define GSTRD 36
#define GEMM_SMEM (2 * 2 * 128 * GSTRD * 4)   // 73728 B

__global__ __launch_bounds__(256, 2) void gemm_tf32_kernel(
    const float* __restrict__ X, const float* __restrict__ W,
    float* __restrict__ outArg, int osel, float alpha)
{
    float* out;
    if (osel == 0) out = g_q;
    else if (osel == 1) out = g_k;
    else if (osel == 2) out = g_v;
    else out = outArg;

    extern __shared__ unsigned gsm[];
    unsigned* As = gsm;                       // [2][128][GSTRD]
    unsigned* Bs = gsm + 2 * 128 * GSTRD;

    const int tid  = threadIdx.x;
    const int lane = tid & 31;
    const int wid  = tid >> 5;
    const int wm   = (wid & 3) * 32;
    const int wn   = (wid >> 2) * 64;
    const int g    = lane >> 2;
    const int t    = lane & 3;
    const int m0   = blockIdx.y * 128;
    const int n0   = blockIdx.x * 128;

    // staging pattern: thread covers 4 (row, col4) pairs per array
    const int sr[1] = {0};
    float acc[2][8][4];
#pragma unroll
    for (int mt = 0; mt < 2; mt++)
#pragma unroll
        for (int nt = 0; nt < 8; nt++)
#pragma unroll
            for (int i = 0; i < 4; i++) acc[mt][nt][i] = 0.f;
    (void)sr;

    auto stage = [&](int buf, int k0) {
        unsigned* Ab = As + buf * 128 * GSTRD;
        unsigned* Bb = Bs + buf * 128 * GSTRD;
#pragma unroll
        for (int l = 0; l < 4; l++) {
            int idx = tid + l * 256;          // 0..1023
            int r = idx >> 3;                 // 0..127
            int c = (idx & 7) * 4;            // 0..28
            cp_async16(&Ab[r * GSTRD + c], X + (size_t)(m0 + r) * NC + k0 + c);
            cp_async16(&Bb[r * GSTRD + c], W + (size_t)(n0 + r) * NC + k0 + c);
        }
        cp_commit();
    };

    stage(0, 0);

    const int NCHUNK = NC / 32;   // 32
    for (int ch = 0; ch < NCHUNK; ch++) {
        int buf = ch & 1;
        if (ch + 1 < NCHUNK) {
            stage(buf ^ 1, (ch + 1) * 32);
            cp_wait<1>();
        } else {
            cp_wait<0>();
        }
        __syncthreads();

        const unsigned* Ab = As + buf * 128 * GSTRD;
        const unsigned* Bb = Bs + buf * 128 * GSTRD;
#pragma unroll
        for (int kk = 0; kk < 4; kk++) {
            const int kb = kk * 8;
            unsigned a[2][4], b[8][2];
#pragma unroll
            for (int mt = 0; mt < 2; mt++) {
                int row = wm + mt * 16 + g;
                a[mt][0] = Ab[row * GSTRD + kb + t];
                a[mt][1] = Ab[(row + 8) * GSTRD + kb + t];
                a[mt][2] = Ab[row * GSTRD + kb + t + 4];
                a[mt][3] = Ab[(row + 8) * GSTRD + kb + t + 4];
            }
#pragma unroll
            for (int nt = 0; nt < 8; nt++) {
                int col = wn + nt * 8 + g;
                b[nt][0] = Bb[col * GSTRD + kb + t];
                b[nt][1] = Bb[col * GSTRD + kb + t + 4];
            }
#pragma unroll
            for (int mt = 0; mt < 2; mt++)
#pragma unroll
                for (int nt = 0; nt < 8; nt++)
                    mma_tf32(acc[mt][nt], a[mt], b[nt]);
        }
        __syncthreads();
    }

#pragma unroll
    for (int mt = 0; mt < 2; mt++) {
#pragma unroll
        for (int nt = 0; nt < 8; nt++) {
            int m1 = m0 + wm + mt * 16 + g;
            int n  = n0 + wn + nt * 8 + t * 2;
#pragma unroll
            for (int half = 0; half < 2; half++) {
                int m = m1 + half * 8;
                float2 vv = make_float2(acc[mt][nt][half*2] * alpha,
                                        acc[mt][nt][half*2+1] * alpha);
                if (osel < 3) {
                    int bb = m >> 11;
                    int tt = m & (NT - 1);
                    int h  = n >> 6;
                    int d  = n & 63;
                    *(float2*)&out[(((size_t)bb * NH + h) * NT + tt) * ND + d] = vv;
                } else {
                    *(float2*)&out[(size_t)m * NC + n] = vv;
                }
            }
        }
    }
}

// ---------------------------------------------------------------------------
// Flash attention with tf32 mma.  128 queries x 64-key tiles, 8 warps,
// warp = 16 query rows x full 64 keys.  Softmax stats in registers.
// Q pre-scaled by 0.125*log2(e); exp2f softmax.  Output written rna-rounded
// into g_xt (input of the final GEMM), layout [B,T,C].
// ---------------------------------------------------------------------------
#define PSTRD 68
#define VSTRD 72
#define ATT_SMEM ((128*PSTRD + 64*PSTRD + 64*VSTRD) * 4)   // 70656 B

__global__ __launch_bounds__(256) void attn_kernel()
{
    extern __shared__ unsigned asm_[];
    unsigned* Pu = asm_;                       // [128][PSTRD]  (Q staging, then P)
    unsigned* Ku = Pu + 128 * PSTRD;           // [64][PSTRD]
    unsigned* Vu = Ku + 64 * PSTRD;            // [64][VSTRD]

    const int tid  = threadIdx.x;
    const int lane = tid & 31;
    const int wid  = tid >> 5;
    const int wm   = wid * 16;                 // warp's query-row base
    const int g    = lane >> 2;
    const int t    = lane & 3;

    const int bh = blockIdx.y;
    const int qb = gridDim.x - 1 - blockIdx.x;   // heavy blocks first
    const int q0 = qb * 128;

    const float* qp = g_q + (size_t)bh * NT * ND;
    const float* kp = g_k + (size_t)bh * NT * ND;
    const float* vp = g_v + (size_t)bh * NT * ND;

    // stage Q tile (128x64) into Pu with tf32 rounding
#pragma unroll
    for (int l = 0; l < 8; l++) {
        int idx = tid + l * 256;               // 0..2047
        int r = idx >> 4, c = (idx & 15) * 4;
        float4 v = *(const float4*)(qp + (size_t)(q0 + r) * ND + c);
        uint4 u = make_uint4(f2tf32(v.x), f2tf32(v.y), f2tf32(v.z), f2tf32(v.w));
        *(uint4*)&Pu[r * PSTRD + c] = u;
    }
    __syncthreads();

    // Q fragments -> registers (warp-private rows)
    unsigned aq[8][4];
#pragma unroll
    for (int kk = 0; kk < 8; kk++) {
        int kb = kk * 8;
        aq[kk][0] = Pu[(wm + g) * PSTRD + kb + t];
        aq[kk][1] = Pu[(wm + g + 8) * PSTRD + kb + t];
        aq[kk][2] = Pu[(wm + g) * PSTRD + kb + t + 4];
        aq[kk][3] = Pu[(wm + g + 8) * PSTRD + kb + t + 4];
    }

    float o[8][4];
#pragma unroll
    for (int nd = 0; nd < 8; nd++)
#pragma unroll
        for (int i = 0; i < 4; i++) o[nd][i] = 0.f;
    float m0r = -INFINITY, m1r = -INFINITY, l0r = 0.f, l1r = 0.f;

    const int r0g = q0 + wm + g;       // this thread's two global query rows
    const int r1g = r0g + 8;

    const int ntile = q0 / 64 + 2;
    for (int kt = 0; kt < ntile; kt++) {
        const int k0 = kt * 64;
        __syncthreads();   // protect Ku/Vu from in-flight reads of prev iter

        // stage K, V (64x64 each) with tf32 rounding
#pragma unroll
        for (int l = 0; l < 4; l++) {
            int idx = tid + l * 256;
            int r = idx >> 4, c = (idx & 15) * 4;
            float4 kvv = *(const float4*)(kp + (size_t)(k0 + r) * ND + c);
            *(uint4*)&Ku[r * PSTRD + c] =
                make_uint4(f2tf32(kvv.x), f2tf32(kvv.y), f2tf32(kvv.z), f2tf32(kvv.w));
            float4 vvv = *(const float4*)(vp + (size_t)(k0 + r) * ND + c);
            *(uint4*)&Vu[r * VSTRD + c] =
                make_uint4(f2tf32(vvv.x), f2tf32(vvv.y), f2tf32(vvv.z), f2tf32(vvv.w));
        }
        __syncthreads();

        // S = Q K^T  (16x64 per warp)
        float s[8][4];
#pragma unroll
        for (int nt = 0; nt < 8; nt++)
#pragma unroll
            for (int i = 0; i < 4; i++) s[nt][i] = 0.f;
#pragma unroll
        for (int kk = 0; kk < 8; kk++) {
            int kb = kk * 8;
#pragma unroll
            for (int nt = 0; nt < 8; nt++) {
                unsigned b[2];
                b[0] = Ku[(nt * 8 + g) * PSTRD + kb + t];
                b[1] = Ku[(nt * 8 + g) * PSTRD + kb + t + 4];
                mma_tf32(s[nt], aq[kk], b);
            }
        }

        // causal mask (only tiles overlapping the diagonal)
        if (kt >= ntile - 2) {
#pragma unroll
            for (int nt = 0; nt < 8; nt++) {
                int c0 = k0 + nt * 8 + t * 2;
                if (c0 > r0g)     s[nt][0] = -INFINITY;
                if (c0 + 1 > r0g) s[nt][1] = -INFINITY;
                if (c0 > r1g)     s[nt][2] = -INFINITY;
                if (c0 + 1 > r1g) s[nt][3] = -INFINITY;
            }
        }

        // online softmax (register stats; rows owned by 4-lane groups)
        float ml0 = -INFINITY, ml1 = -INFINITY;
#pragma unroll
        for (int nt = 0; nt < 8; nt++) {
            ml0 = fmaxf(ml0, fmaxf(s[nt][0], s[nt][1]));
            ml1 = fmaxf(ml1, fmaxf(s[nt][2], s[nt][3]));
        }
        ml0 = fmaxf(ml0, __shfl_xor_sync(0xffffffffu, ml0, 1));
        ml0 = fmaxf(ml0, __shfl_xor_sync(0xffffffffu, ml0, 2));
        ml1 = fmaxf(ml1, __shfl_xor_sync(0xffffffffu, ml1, 1));
        ml1 = fmaxf(ml1, __shfl_xor_sync(0xffffffffu, ml1, 2));
        float mn0 = fmaxf(m0r, ml0), mn1 = fmaxf(m1r, ml1);
        float sc0 = exp2f(m0r - mn0), sc1 = exp2f(m1r - mn1);

        float sum0 = 0.f, sum1 = 0.f;
#pragma unroll
        for (int nt = 0; nt < 8; nt++) {
            float p0 = exp2f(s[nt][0] - mn0);
            float p1 = exp2f(s[nt][1] - mn0);
            float p2 = exp2f(s[nt][2] - mn1);
            float p3 = exp2f(s[nt][3] - mn1);
            sum0 += p0 + p1; sum1 += p2 + p3;
            *(uint2*)&Pu[(wm + g) * PSTRD + nt * 8 + t * 2] =
                make_uint2(f2tf32(p0), f2tf32(p1));
            *(uint2*)&Pu[(wm + g + 8) * PSTRD + nt * 8 + t * 2] =
                make_uint2(f2tf32(p2), f2tf32(p3));
        }
        sum0 += __shfl_xor_sync(0xffffffffu, sum0, 1);
        sum0 += __shfl_xor_sync(0xffffffffu, sum0, 2);
        sum1 += __shfl_xor_sync(0xffffffffu, sum1, 1);
        sum1 += __shfl_xor_sync(0xffffffffu, sum1, 2);
        l0r = l0r * sc0 + sum0; m0r = mn0;
        l1r = l1r * sc1 + sum1; m1r = mn1;

        // rescale O and accumulate P V  (P is warp-private: no barrier needed)
#pragma unroll
        for (int nd = 0; nd < 8; nd++) {
            o[nd][0] *= sc0; o[nd][1] *= sc0;
            o[nd][2] *= sc1; o[nd][3] *= sc1;
        }
#pragma unroll
        for (int kk = 0; kk < 8; kk++) {
            int kb = kk * 8;
            unsigned a[4];
            a[0] = Pu[(wm + g) * PSTRD + kb + t];
            a[1] = Pu[(wm + g + 8) * PSTRD + kb + t];
            a[2] = Pu[(wm + g) * PSTRD + kb + t + 4];
            a[3] = Pu[(wm + g + 8) * PSTRD + kb + t + 4];
#pragma unroll
            for (int nd = 0; nd < 8; nd++) {
                unsigned b[2];
                b[0] = Vu[(kb + t) * VSTRD + nd * 8 + g];
                b[1] = Vu[(kb + t + 4) * VSTRD + nd * 8 + g];
                mma_tf32(o[nd], a, b);
            }
        }
    }

    // epilogue: normalize, rna-round, write [B,T,C] into g_xt
    const int bb = bh >> 4;
    const int h  = bh & 15;
    float inv0 = 1.f / l0r, inv1 = 1.f / l1r;
#pragma unroll
    for (int nd = 0; nd < 8; nd++) {
        int d = nd * 8 + t * 2;
        size_t base0 = ((size_t)(bb * NT + r0g)) * NC + h * ND + d;
        size_t base1 = ((size_t)(bb * NT + r1g)) * NC + h * ND + d;
        *(uint2*)&g_xt[base0] = make_uint2(f2tf32(o[nd][0]*inv0), f2tf32(o[nd][1]*inv0));
        *(uint2*)&g_xt[base1] = make_uint2(f2tf32(o[nd][2]*inv1), f2tf32(o[nd][3]*inv1));
    }
}

// ---------------------------------------------------------------------------
extern "C" void kernel_launch(void* const* d_in, const int* in_sizes, int n_in,
                              void* d_out, int out_size)
{
    const float* x  = (const float*)d_in[0];
    const float* Wq = (const float*)d_in[1];
    const float* Wk = (const float*)d_in[2];
    const float* Wv = (const float*)d_in[3];
    const float* Wp = (const float*)d_in[4];
    float* out = (float*)d_out;

    cudaFuncSetAttribute(gemm_tf32_kernel, cudaFuncAttributeMaxDynamicSharedMemorySize,
                         GEMM_SMEM);
    cudaFuncSetAttribute(attn_kernel, cudaFuncAttributeMaxDynamicSharedMemorySize,
                         (int)ATT_SMEM);

    // resolve device-global scratch addresses (host-side, capture-safe)
    float *xt, *wq, *wk, *wv, *wp;
    cudaGetSymbolAddress((void**)&xt, g_xt);
    cudaGetSymbolAddress((void**)&wq, g_wq);
    cudaGetSymbolAddress((void**)&wk, g_wk);
    cudaGetSymbolAddress((void**)&wv, g_wv);
    cudaGetSymbolAddress((void**)&wp, g_wp);

    // pre-round inputs to tf32
    cvt_tf32_kernel<<<(BT*NC/4 + 255)/256, 256>>>(x,  xt, BT*NC/4);
    cvt_tf32_kernel<<<(NC*NC/4 + 255)/256, 256>>>(Wq, wq, NC*NC/4);
    cvt_tf32_kernel<<<(NC*NC/4 + 255)/256, 256>>>(Wk, wk, NC*NC/4);
    cvt_tf32_kernel<<<(NC*NC/4 + 255)/256, 256>>>(Wv, wv, NC*NC/4);
    cvt_tf32_kernel<<<(NC*NC/4 + 255)/256, 256>>>(Wp, wp, NC*NC/4);

    dim3 ggrid(NC / 128, BT / 128);   // (8, 64)
    const float aq_scale = 0.125f * 1.4426950408889634f;   // 1/sqrt(D) * log2(e)

    gemm_tf32_kernel<<<ggrid, 256, GEMM_SMEM>>>(xt, wq, nullptr, 0, aq_scale);
    gemm_tf32_kernel<<<ggrid, 256, GEMM_SMEM>>>(xt, wk, nullptr, 1, 1.0f);
    gemm_tf32_kernel<<<ggrid, 256, GEMM_SMEM>>>(xt, wv, nullptr, 2, 1.0f);

    attn_kernel<<<dim3(NT / 128, NB * NH), 256, ATT_SMEM>>>();   // writes g_xt

    gemm_tf32_kernel<<<ggrid, 256, GEMM_SMEM>>>(xt, wp, out, 3, 1.0f);
}

// round 10
// speedup vs baseline: 4.1905x; 1.0341x over previous
#include <cuda_runtime.h>
#include <math.h>

#define NB 4
#define NT 2048
#define NC 1024
#define NH 16
#define ND 64
#define BT (NB*NT)   // 8192

// Scratch (static device globals)
__device__ float g_q[NB*NH*NT*ND];   // [B,H,T,D], tf32 bits, scaled by 0.125*log2(e)
__device__ float g_k[NB*NH*NT*ND];   // tf32 bits
__device__ float g_v[NB*NH*NT*ND];   // tf32 bits
__device__ float g_xt[BT*NC];        // tf32-rounded GEMM A input (x, then attn out)
__device__ float g_wq[NC*NC];        // tf32-rounded weights
__device__ float g_wk[NC*NC];
__device__ float g_wv[NC*NC];
__device__ float g_wp[NC*NC];

__device__ __forceinline__ unsigned f2tf32(float x) {
    unsigned r;
    asm("cvt.rna.tf32.f32 %0, %1;" : "=r"(r) : "f"(x));
    return r;
}

__device__ __forceinline__ void mma_tf32(float c[4], const unsigned a[4], const unsigned b[2]) {
    asm volatile(
        "mma.sync.aligned.m16n8k8.row.col.f32.tf32.tf32.f32 "
        "{%0,%1,%2,%3}, {%4,%5,%6,%7}, {%8,%9}, {%0,%1,%2,%3};"
        : "+f"(c[0]), "+f"(c[1]), "+f"(c[2]), "+f"(c[3])
        : "r"(a[0]), "r"(a[1]), "r"(a[2]), "r"(a[3]), "r"(b[0]), "r"(b[1]));
}

__device__ __forceinline__ void cp_async16(void* smem, const void* gmem) {
    unsigned s = (unsigned)__cvta_generic_to_shared(smem);
    asm volatile("cp.async.cg.shared.global [%0], [%1], 16;\n" :: "r"(s), "l"(gmem));
}
__device__ __forceinline__ void cp_commit() { asm volatile("cp.async.commit_group;\n" ::); }
template<int N> __device__ __forceinline__ void cp_wait() {
    asm volatile("cp.async.wait_group %0;\n" :: "n"(N));
}

// XOR swizzle for stride-64-float tiles, 16B granularity.
// f maps row&7 injectively; for rows varying in low 2 bits (V pattern) it feeds
// bits[1:2], keeping bit0 for the column-unit bit -> conflict-free both ways.
__device__ __forceinline__ int fsw(int r7) { return ((r7 & 3) << 1) | (r7 >> 2); }
__device__ __forceinline__ int swz(int row, int col) {
    return (row << 6) + ((((col >> 2) ^ fsw(row & 7)) << 2) | (col & 3));
}

// ---------------------------------------------------------------------------
// Elementwise rna-round to tf32 (bits stored as float). n multiple of 4.
// ---------------------------------------------------------------------------
__global__ void cvt_tf32_kernel(const float* __restrict__ src, float* __restrict__ dst, int n4)
{
    int i = blockIdx.x * blockDim.x + threadIdx.x;
    if (i < n4) {
        float4 v = ((const float4*)src)[i];
        uint4 u = make_uint4(f2tf32(v.x), f2tf32(v.y), f2tf32(v.z), f2tf32(v.w));
        ((uint4*)dst)[i] = u;
    }
}

// ---------------------------------------------------------------------------
// tf32 GEMM (cp.async, double-buffered, 1 barrier/chunk): out = alpha*(X@W^T).
// X, W PRE-ROUNDED tf32 bits. Block 128x128, 8 warps (4m x 2n), k-chunk 32.
// osel 0/1/2: scatter rna-rounded to g_q/g_k/g_v as [B,H,T,D];
// osel 3: plain fp32 row-major to outArg.
// ---------------------------------------------------------------------------
#define GSTRD 36
#define GEMM_SMEM (2 * 2 * 128 * GSTRD * 4)   // 73728 B

__global__ __launch_bounds__(256, 2) void gemm_tf32_kernel(
    const float* __restrict__ X, const float* __restrict__ W,
    float* __restrict__ outArg, int osel, float alpha)
{
    float* out;
    if (osel == 0) out = g_q;
    else if (osel == 1) out = g_k;
    else if (osel == 2) out = g_v;
    else out = outArg;

    extern __shared__ unsigned gsm[];
    unsigned* As = gsm;                       // [2][128][GSTRD]
    unsigned* Bs = gsm + 2 * 128 * GSTRD;

    const int tid  = threadIdx.x;
    const int lane = tid & 31;
    const int wid  = tid >> 5;
    const int wm   = (wid & 3) * 32;
    const int wn   = (wid >> 2) * 64;
    const int g    = lane >> 2;
    const int t    = lane & 3;
    const int m0   = blockIdx.y * 128;
    const int n0   = blockIdx.x * 128;

    float acc[2][8][4];
#pragma unroll
    for (int mt = 0; mt < 2; mt++)
#pragma unroll
        for (int nt = 0; nt < 8; nt++)
#pragma unroll
            for (int i = 0; i < 4; i++) acc[mt][nt][i] = 0.f;

    auto stage = [&](int buf, int k0) {
        unsigned* Ab = As + buf * 128 * GSTRD;
        unsigned* Bb = Bs + buf * 128 * GSTRD;
#pragma unroll
        for (int l = 0; l < 4; l++) {
            int idx = tid + l * 256;          // 0..1023
            int r = idx >> 3;                 // 0..127
            int c = (idx & 7) * 4;            // 0..28
            cp_async16(&Ab[r * GSTRD + c], X + (size_t)(m0 + r) * NC + k0 + c);
            cp_async16(&Bb[r * GSTRD + c], W + (size_t)(n0 + r) * NC + k0 + c);
        }
        cp_commit();
    };

    stage(0, 0);

    const int NCHUNK = NC / 32;   // 32
    for (int ch = 0; ch < NCHUNK; ch++) {
        int buf = ch & 1;
        cp_wait<0>();
        __syncthreads();                       // data visible; prev readers done
        if (ch + 1 < NCHUNK) stage(buf ^ 1, (ch + 1) * 32);  // overlaps compute

        const unsigned* Ab = As + buf * 128 * GSTRD;
        const unsigned* Bb = Bs + buf * 128 * GSTRD;
#pragma unroll
        for (int kk = 0; kk < 4; kk++) {
            const int kb = kk * 8;
            unsigned a[2][4], b[8][2];
#pragma unroll
            for (int mt = 0; mt < 2; mt++) {
                int row = wm + mt * 16 + g;
                a[mt][0] = Ab[row * GSTRD + kb + t];
                a[mt][1] = Ab[(row + 8) * GSTRD + kb + t];
                a[mt][2] = Ab[row * GSTRD + kb + t + 4];
                a[mt][3] = Ab[(row + 8) * GSTRD + kb + t + 4];
            }
#pragma unroll
            for (int nt = 0; nt < 8; nt++) {
                int col = wn + nt * 8 + g;
                b[nt][0] = Bb[col * GSTRD + kb + t];
                b[nt][1] = Bb[col * GSTRD + kb + t + 4];
            }
#pragma unroll
            for (int mt = 0; mt < 2; mt++)
#pragma unroll
                for (int nt = 0; nt < 8; nt++)
                    mma_tf32(acc[mt][nt], a[mt], b[nt]);
        }
    }

#pragma unroll
    for (int mt = 0; mt < 2; mt++) {
#pragma unroll
        for (int nt = 0; nt < 8; nt++) {
            int m1 = m0 + wm + mt * 16 + g;
            int n  = n0 + wn + nt * 8 + t * 2;
#pragma unroll
            for (int half = 0; half < 2; half++) {
                int m = m1 + half * 8;
                float v0 = acc[mt][nt][half*2] * alpha;
                float v1 = acc[mt][nt][half*2+1] * alpha;
                if (osel < 3) {
                    int bb = m >> 11;
                    int tt = m & (NT - 1);
                    int h  = n >> 6;
                    int d  = n & 63;
                    // round to tf32 here so attention can stage raw bytes
                    *(uint2*)&out[(((size_t)bb * NH + h) * NT + tt) * ND + d] =
                        make_uint2(f2tf32(v0), f2tf32(v1));
                } else {
                    *(float2*)&out[(size_t)m * NC + n] = make_float2(v0, v1);
                }
            }
        }
    }
}

// ---------------------------------------------------------------------------
// Flash attention, tf32 mma, cp.async double-buffered K/V, XOR-swizzled smem.
// 128 queries x 64-key tiles, 8 warps (16 query rows each), stats in regs.
// Q/K/V in gmem are already tf32 bits (GEMM epilogue), Q pre-scaled.
// P aliases the Q buffer (warp-private rows). One __syncthreads per tile.
// Output rna-rounded into g_xt [B,T,C].
// ---------------------------------------------------------------------------
#define ATT_SMEM ((128*64 + 2*64*64 + 2*64*64) * 4)   // 98304 B

__global__ __launch_bounds__(256, 2) void attn_kernel()
{
    extern __shared__ unsigned asm_[];
    unsigned* QP = asm_;                 // [128][64] swizzled: Q staging then P
    unsigned* Kb = asm_ + 128 * 64;      // [2][64][64] swizzled
    unsigned* Vb = Kb + 2 * 64 * 64;     // [2][64][64] swizzled

    const int tid  = threadIdx.x;
    const int lane = tid & 31;
    const int wid  = tid >> 5;
    const int wm   = wid * 16;
    const int g    = lane >> 2;
    const int t    = lane & 3;

    const int bh = blockIdx.y;
    const int qb = gridDim.x - 1 - blockIdx.x;   // heavy blocks first
    const int q0 = qb * 128;

    const float* qp = g_q + (size_t)bh * NT * ND;
    const float* kp = g_k + (size_t)bh * NT * ND;
    const float* vp = g_v + (size_t)bh * NT * ND;

    auto stageKV = [&](int buf, int k0) {
        unsigned* kd = Kb + buf * 64 * 64;
        unsigned* vd = Vb + buf * 64 * 64;
#pragma unroll
        for (int l = 0; l < 4; l++) {
            int idx = tid + l * 256;          // 0..1023
            int r = idx >> 4;                 // 0..63
            int u = idx & 15;                 // 16B unit
            int d = r * 64 + ((u ^ fsw(r & 7)) << 2);
            cp_async16(&kd[d], kp + (size_t)(k0 + r) * ND + u * 4);
            cp_async16(&vd[d], vp + (size_t)(k0 + r) * ND + u * 4);
        }
        cp_commit();
    };

    // prologue: Q (group 1), then K0/V0 (group 2)
#pragma unroll
    for (int l = 0; l < 8; l++) {
        int idx = tid + l * 256;              // 0..2047
        int r = idx >> 4;                     // 0..127
        int u = idx & 15;
        int d = r * 64 + ((u ^ fsw(r & 7)) << 2);
        cp_async16(&QP[d], qp + (size_t)(q0 + r) * ND + u * 4);
    }
    cp_commit();
    stageKV(0, 0);

    cp_wait<1>();          // Q arrived (K0/V0 may still be in flight)
    __syncthreads();

    // Q fragments -> registers
    unsigned aq[8][4];
#pragma unroll
    for (int kk = 0; kk < 8; kk++) {
        int kb = kk * 8;
        aq[kk][0] = QP[swz(wm + g,     kb + t)];
        aq[kk][1] = QP[swz(wm + g + 8, kb + t)];
        aq[kk][2] = QP[swz(wm + g,     kb + t + 4)];
        aq[kk][3] = QP[swz(wm + g + 8, kb + t + 4)];
    }

    float o[8][4];
#pragma unroll
    for (int nd = 0; nd < 8; nd++)
#pragma unroll
        for (int i = 0; i < 4; i++) o[nd][i] = 0.f;
    float m0r = -INFINITY, m1r = -INFINITY, l0r = 0.f, l1r = 0.f;

    const int r0g = q0 + wm + g;
    const int r1g = r0g + 8;

    const int ntile = q0 / 64 + 2;
    for (int kt = 0; kt < ntile; kt++) {
        cp_wait<0>();
        __syncthreads();                       // tile kt visible; prev readers done
        if (kt + 1 < ntile) stageKV((kt + 1) & 1, (kt + 1) * 64);  // overlaps compute

        const unsigned* Kc = Kb + (kt & 1) * 64 * 64;
        const unsigned* Vc = Vb + (kt & 1) * 64 * 64;

        // S = Q K^T  (16x64 per warp)
        float s[8][4];
#pragma unroll
        for (int nt = 0; nt < 8; nt++)
#pragma unroll
            for (int i = 0; i < 4; i++) s[nt][i] = 0.f;
#pragma unroll
        for (int kk = 0; kk < 8; kk++) {
            int kb = kk * 8;
#pragma unroll
            for (int nt = 0; nt < 8; nt++) {
                unsigned b[2];
                b[0] = Kc[swz(nt * 8 + g, kb + t)];
                b[1] = Kc[swz(nt * 8 + g, kb + t + 4)];
                mma_tf32(s[nt], aq[kk], b);
            }
        }

        // causal mask on diagonal-overlapping tiles
        if (kt >= ntile - 2) {
            const int k0 = kt * 64;
#pragma unroll
            for (int nt = 0; nt < 8; nt++) {
                int c0 = k0 + nt * 8 + t * 2;
                if (c0 > r0g)     s[nt][0] = -INFINITY;
                if (c0 + 1 > r0g) s[nt][1] = -INFINITY;
                if (c0 > r1g)     s[nt][2] = -INFINITY;
                if (c0 + 1 > r1g) s[nt][3] = -INFINITY;
            }
        }

        // online softmax (register stats)
        float ml0 = -INFINITY, ml1 = -INFINITY;
#pragma unroll
        for (int nt = 0; nt < 8; nt++) {
            ml0 = fmaxf(ml0, fmaxf(s[nt][0], s[nt][1]));
            ml1 = fmaxf(ml1, fmaxf(s[nt][2], s[nt][3]));
        }
        ml0 = fmaxf(ml0, __shfl_xor_sync(0xffffffffu, ml0, 1));
        ml0 = fmaxf(ml0, __shfl_xor_sync(0xffffffffu, ml0, 2));
        ml1 = fmaxf(ml1, __shfl_xor_sync(0xffffffffu, ml1, 1));
        ml1 = fmaxf(ml1, __shfl_xor_sync(0xffffffffu, ml1, 2));
        float mn0 = fmaxf(m0r, ml0), mn1 = fmaxf(m1r, ml1);
        float sc0 = exp2f(m0r - mn0), sc1 = exp2f(m1r - mn1);

        float sum0 = 0.f, sum1 = 0.f;
#pragma unroll
        for (int nt = 0; nt < 8; nt++) {
            float p0 = exp2f(s[nt][0] - mn0);
            float p1 = exp2f(s[nt][1] - mn0);
            float p2 = exp2f(s[nt][2] - mn1);
            float p3 = exp2f(s[nt][3] - mn1);
            sum0 += p0 + p1; sum1 += p2 + p3;
            *(uint2*)&QP[swz(wm + g,     nt * 8 + t * 2)] = make_uint2(f2tf32(p0), f2tf32(p1));
            *(uint2*)&QP[swz(wm + g + 8, nt * 8 + t * 2)] = make_uint2(f2tf32(p2), f2tf32(p3));
        }
        sum0 += __shfl_xor_sync(0xffffffffu, sum0, 1);
        sum0 += __shfl_xor_sync(0xffffffffu, sum0, 2);
        sum1 += __shfl_xor_sync(0xffffffffu, sum1, 1);
        sum1 += __shfl_xor_sync(0xffffffffu, sum1, 2);
        l0r = l0r * sc0 + sum0; m0r = mn0;
        l1r = l1r * sc1 + sum1; m1r = mn1;

        __syncwarp();   // P smem handoff is cross-lane within the warp

        // rescale O, accumulate P V
#pragma unroll
        for (int nd = 0; nd < 8; nd++) {
            o[nd][0] *= sc0; o[nd][1] *= sc0;
            o[nd][2] *= sc1; o[nd][3] *= sc1;
        }
#pragma unroll
        for (int kk = 0; kk < 8; kk++) {
            int kb = kk * 8;
            unsigned a[4];
            a[0] = QP[swz(wm + g,     kb + t)];
            a[1] = QP[swz(wm + g + 8, kb + t)];
            a[2] = QP[swz(wm + g,     kb + t + 4)];
            a[3] = QP[swz(wm + g + 8, kb + t + 4)];
#pragma unroll
            for (int nd = 0; nd < 8; nd++) {
                unsigned b[2];
                b[0] = Vc[swz(kb + t,     nd * 8 + g)];
                b[1] = Vc[swz(kb + t + 4, nd * 8 + g)];
                mma_tf32(o[nd], a, b);
            }
        }
    }

    // epilogue: normalize, rna-round, write [B,T,C] into g_xt
    const int bb = bh >> 4;
    const int h  = bh & 15;
    float inv0 = 1.f / l0r, inv1 = 1.f / l1r;
#pragma unroll
    for (int nd = 0; nd < 8; nd++) {
        int d = nd * 8 + t * 2;
        size_t base0 = ((size_t)(bb * NT + r0g)) * NC + h * ND + d;
        size_t base1 = ((size_t)(bb * NT + r1g)) * NC + h * ND + d;
        *(uint2*)&g_xt[base0] = make_uint2(f2tf32(o[nd][0]*inv0), f2tf32(o[nd][1]*inv0));
        *(uint2*)&g_xt[base1] = make_uint2(f2tf32(o[nd][2]*inv1), f2tf32(o[nd][3]*inv1));
    }
}

// ---------------------------------------------------------------------------
extern "C" void kernel_launch(void* const* d_in, const int* in_sizes, int n_in,
                              void* d_out, int out_size)
{
    const float* x  = (const float*)d_in[0];
    const float* Wq = (const float*)d_in[1];
    const float* Wk = (const float*)d_in[2];
    const float* Wv = (const float*)d_in[3];
    const float* Wp = (const float*)d_in[4];
    float* out = (float*)d_out;

    cudaFuncSetAttribute(gemm_tf32_kernel, cudaFuncAttributeMaxDynamicSharedMemorySize,
                         GEMM_SMEM);
    cudaFuncSetAttribute(attn_kernel, cudaFuncAttributeMaxDynamicSharedMemorySize,
                         (int)ATT_SMEM);

    float *xt, *wq, *wk, *wv, *wp;
    cudaGetSymbolAddress((void**)&xt, g_xt);
    cudaGetSymbolAddress((void**)&wq, g_wq);
    cudaGetSymbolAddress((void**)&wk, g_wk);
    cudaGetSymbolAddress((void**)&wv, g_wv);
    cudaGetSymbolAddress((void**)&wp, g_wp);

    // pre-round GEMM inputs to tf32
    cvt_tf32_kernel<<<(BT*NC/4 + 255)/256, 256>>>(x,  xt, BT*NC/4);
    cvt_tf32_kernel<<<(NC*NC/4 + 255)/256, 256>>>(Wq, wq, NC*NC/4);
    cvt_tf32_kernel<<<(NC*NC/4 + 255)/256, 256>>>(Wk, wk, NC*NC/4);
    cvt_tf32_kernel<<<(NC*NC/4 + 255)/256, 256>>>(Wv, wv, NC*NC/4);
    cvt_tf32_kernel<<<(NC*NC/4 + 255)/256, 256>>>(Wp, wp, NC*NC/4);

    dim3 ggrid(NC / 128, BT / 128);   // (8, 64)
    const float aq_scale = 0.125f * 1.4426950408889634f;   // 1/sqrt(D) * log2(e)

    gemm_tf32_kernel<<<ggrid, 256, GEMM_SMEM>>>(xt, wq, nullptr, 0, aq_scale);
    gemm_tf32_kernel<<<ggrid, 256, GEMM_SMEM>>>(xt, wk, nullptr, 1, 1.0f);
    gemm_tf32_kernel<<<ggrid, 256, GEMM_SMEM>>>(xt, wv, nullptr, 2, 1.0f);

    attn_kernel<<<dim3(NT / 128, NB * NH), 256, ATT_SMEM>>>();   // writes g_xt

    gemm_tf32_kernel<<<ggrid, 256, GEMM_SMEM>>>(xt, wp, out, 3, 1.0f);
}